// round 4
// baseline (speedup 1.0000x reference)
#include <cuda_runtime.h>

// SVF 3D scaling-and-squaring, hybrid layout:
//   steps 0..13  : split float2(x,y) + float(z)  (coherent-gather optimal)
//   step  14     : split -> float4 transition
//   steps 15..18 : float4 -> float4              (scattered-gather optimal)
//   step  19     : float4 -> planar output (fused final)
// disp0 = v / 2^20 ; out = [transformation ; displacement], each [2,3,128^3] f32.

#define NVOX (1 << 21)              // 128^3
#define NB 2
#define TOTAL (NB * 3 * NVOX)
#define NUM_STEPS 20
#define INIT_SCALE 9.5367431640625e-07f      // 2^-20

__device__ float2 g_xyA[NB * NVOX];
__device__ float  g_zA [NB * NVOX];
__device__ float2 g_xyB[NB * NVOX];
__device__ float  g_zB [NB * NVOX];
__device__ float4 g_f4A[NB * NVOX];
__device__ float4 g_f4B[NB * NVOX];
__device__ float  g_base[3 * 128];  // (g+1)*63.5 per axis
__device__ float  g_raw [3 * 128];  // raw identity axis values

// ---------------------------------------------------------------------------
__global__ void __launch_bounds__(256) init_kernel(const float* __restrict__ v) {
    int i   = blockIdx.x * 256 + threadIdx.x;   // over NB*NVOX
    int n   = i >> 21;
    int vox = i & (NVOX - 1);
    const float* b = v + ((size_t)n * 3 << 21);
    float2 xy;
    xy.x = b[vox]        * INIT_SCALE;
    xy.y = b[NVOX + vox] * INIT_SCALE;
    g_xyA[i] = xy;
    g_zA[i]  = b[2 * NVOX + vox] * INIT_SCALE;
}

__global__ void base_kernel(const float* __restrict__ grid) {
    int i = threadIdx.x;            // 0..383
    int c = i >> 7;
    int k = i & 127;
    size_t idx;
    if (c == 0)      idx = (size_t)k * 3 + 0;
    else if (c == 1) idx = (size_t)k * 128 * 3 + 1;
    else             idx = (size_t)k * 128 * 128 * 3 + 2;
    float g = grid[idx];
    g_raw[i]  = g;
    g_base[i] = (g + 1.0f) * 63.5f;
}

// ---------------------------------------------------------------------------
// Shared index/weight computation
struct Corners {
    int i000, i001, i010, i011, i100, i101, i110, i111;
    float w000, w001, w010, w011, w100, w101, w110, w111;
    int x, y, z, vox;
};

__device__ __forceinline__ Corners make_corners(int vox, float dx, float dy, float dz) {
    Corners c;
    c.vox = vox;
    c.x = vox & 127;
    c.y = (vox >> 7) & 127;
    c.z = vox >> 14;

    float ix = fminf(fmaxf(fmaf(dx, 63.5f, g_base[c.x]),        0.0f), 127.0f);
    float iy = fminf(fmaxf(fmaf(dy, 63.5f, g_base[128 + c.y]),  0.0f), 127.0f);
    float iz = fminf(fmaxf(fmaf(dz, 63.5f, g_base[256 + c.z]),  0.0f), 127.0f);

    int x0 = (int)ix;  float fx = ix - (float)x0;
    int y0 = (int)iy;  float fy = iy - (float)y0;
    int z0 = (int)iz;  float fz = iz - (float)z0;
    int x1 = min(x0 + 1, 127);
    int y1 = min(y0 + 1, 127);
    int z1 = min(z0 + 1, 127);

    int zy00 = (z0 << 14) + (y0 << 7);
    int zy01 = (z0 << 14) + (y1 << 7);
    int zy10 = (z1 << 14) + (y0 << 7);
    int zy11 = (z1 << 14) + (y1 << 7);
    c.i000 = zy00 + x0; c.i001 = zy00 + x1;
    c.i010 = zy01 + x0; c.i011 = zy01 + x1;
    c.i100 = zy10 + x0; c.i101 = zy10 + x1;
    c.i110 = zy11 + x0; c.i111 = zy11 + x1;

    float gx0 = 1.0f - fx, gy0 = 1.0f - fy, gz0 = 1.0f - fz;
    c.w000 = gz0 * gy0 * gx0; c.w001 = gz0 * gy0 * fx;
    c.w010 = gz0 * fy  * gx0; c.w011 = gz0 * fy  * fx;
    c.w100 = fz  * gy0 * gx0; c.w101 = fz  * gy0 * fx;
    c.w110 = fz  * fy  * gx0; c.w111 = fz  * fy  * fx;
    return c;
}

// ---------------------------------------------------------------------------
// Split-layout step. OUT_F4: write float4 buffer (transition) instead of split.
template <bool OUT_F4>
__global__ void __launch_bounds__(256, 4) step_split(const float2* __restrict__ sxy,
                                                     const float*  __restrict__ sz,
                                                     float2* __restrict__ dxy,
                                                     float*  __restrict__ dz,
                                                     float4* __restrict__ df4) {
    int t   = blockIdx.x * 256 + threadIdx.x;
    int n   = t >> 21;
    int vox = t & (NVOX - 1);

    const float2* pxy = sxy + ((size_t)n << 21);
    const float*  pz  = sz  + ((size_t)n << 21);

    float2 dcur = pxy[vox];
    float  dzc  = pz[vox];

    Corners c = make_corners(vox, dcur.x, dcur.y, dzc);

    float2 a000 = pxy[c.i000], a001 = pxy[c.i001];
    float2 a010 = pxy[c.i010], a011 = pxy[c.i011];
    float2 a100 = pxy[c.i100], a101 = pxy[c.i101];
    float2 a110 = pxy[c.i110], a111 = pxy[c.i111];
    float  b000 = pz[c.i000],  b001 = pz[c.i001];
    float  b010 = pz[c.i010],  b011 = pz[c.i011];
    float  b100 = pz[c.i100],  b101 = pz[c.i101];
    float  b110 = pz[c.i110],  b111 = pz[c.i111];

    float rx = dcur.x + a000.x*c.w000 + a001.x*c.w001 + a010.x*c.w010 + a011.x*c.w011
                      + a100.x*c.w100 + a101.x*c.w101 + a110.x*c.w110 + a111.x*c.w111;
    float ry = dcur.y + a000.y*c.w000 + a001.y*c.w001 + a010.y*c.w010 + a011.y*c.w011
                      + a100.y*c.w100 + a101.y*c.w101 + a110.y*c.w110 + a111.y*c.w111;
    float rz = dzc    + b000*c.w000 + b001*c.w001 + b010*c.w010 + b011*c.w011
                      + b100*c.w100 + b101*c.w101 + b110*c.w110 + b111*c.w111;

    if (!OUT_F4) {
        float2 r; r.x = rx; r.y = ry;
        dxy[t] = r;
        dz[t]  = rz;
    } else {
        float4 r; r.x = rx; r.y = ry; r.z = rz; r.w = 0.0f;
        df4[t] = r;
    }
}

// ---------------------------------------------------------------------------
// Float4-layout step (scattered phase). LAST: write planar output.
template <bool LAST>
__global__ void __launch_bounds__(256, 4) step_f4(const float4* __restrict__ src,
                                                  float4* __restrict__ dst,
                                                  float* __restrict__ out) {
    int t   = blockIdx.x * 256 + threadIdx.x;
    int n   = t >> 21;
    int vox = t & (NVOX - 1);

    const float4* s = src + ((size_t)n << 21);
    float4 d4 = s[vox];

    Corners c = make_corners(vox, d4.x, d4.y, d4.z);

    float4 c000 = s[c.i000], c001 = s[c.i001];
    float4 c010 = s[c.i010], c011 = s[c.i011];
    float4 c100 = s[c.i100], c101 = s[c.i101];
    float4 c110 = s[c.i110], c111 = s[c.i111];

    float rx = d4.x + c000.x*c.w000 + c001.x*c.w001 + c010.x*c.w010 + c011.x*c.w011
                    + c100.x*c.w100 + c101.x*c.w101 + c110.x*c.w110 + c111.x*c.w111;
    float ry = d4.y + c000.y*c.w000 + c001.y*c.w001 + c010.y*c.w010 + c011.y*c.w011
                    + c100.y*c.w100 + c101.y*c.w101 + c110.y*c.w110 + c111.y*c.w111;
    float rz = d4.z + c000.z*c.w000 + c001.z*c.w001 + c010.z*c.w010 + c011.z*c.w011
                    + c100.z*c.w100 + c101.z*c.w101 + c110.z*c.w110 + c111.z*c.w111;

    if (!LAST) {
        float4 r; r.x = rx; r.y = ry; r.z = rz; r.w = 0.0f;
        dst[t] = r;
    } else {
        size_t pb = (size_t)n * 3 << 21;
        out[pb + vox]                      = g_raw[c.x]       + rx;
        out[pb + NVOX + vox]               = g_raw[128 + c.y] + ry;
        out[pb + 2 * NVOX + vox]           = g_raw[256 + c.z] + rz;
        out[TOTAL + pb + vox]              = rx;
        out[TOTAL + pb + NVOX + vox]       = ry;
        out[TOTAL + pb + 2 * NVOX + vox]   = rz;
    }
}

// ---------------------------------------------------------------------------
extern "C" void kernel_launch(void* const* d_in, const int* in_sizes, int n_in,
                              void* d_out, int out_size) {
    const float* v    = (const float*)d_in[0];
    const float* grid = (const float*)d_in[1];
    float* out = (float*)d_out;

    float2 *xyA, *xyB; float *zA, *zB; float4 *f4A, *f4B;
    cudaGetSymbolAddress((void**)&xyA, g_xyA);
    cudaGetSymbolAddress((void**)&xyB, g_xyB);
    cudaGetSymbolAddress((void**)&zA,  g_zA);
    cudaGetSymbolAddress((void**)&zB,  g_zB);
    cudaGetSymbolAddress((void**)&f4A, g_f4A);
    cudaGetSymbolAddress((void**)&f4B, g_f4B);

    const int blocks = (NB * NVOX) / 256;

    init_kernel<<<blocks, 256>>>(v);
    base_kernel<<<1, 384>>>(grid);

    // steps 0..13 : split ping-pong (A->B, B->A, ... ends in A after s13)
    for (int s = 0; s < 14; s++) {
        bool odd = (s & 1);
        step_split<false><<<blocks, 256>>>(odd ? xyB : xyA, odd ? zB : zA,
                                           odd ? xyA : xyB, odd ? zA : zB, nullptr);
    }
    // step 14 : split(A) -> float4(B)
    step_split<true><<<blocks, 256>>>(xyA, zA, nullptr, nullptr, f4B);
    // steps 15..18 : float4 ping-pong  (B->A, A->B, B->A, A->B)
    step_f4<false><<<blocks, 256>>>(f4B, f4A, nullptr);
    step_f4<false><<<blocks, 256>>>(f4A, f4B, nullptr);
    step_f4<false><<<blocks, 256>>>(f4B, f4A, nullptr);
    step_f4<false><<<blocks, 256>>>(f4A, f4B, nullptr);
    // step 19 : float4(B) -> planar out
    step_f4<true><<<blocks, 256>>>(f4B, nullptr, out);
}

// round 6
// speedup vs baseline: 1.0338x; 1.0338x over previous
#include <cuda_runtime.h>

// SVF 3D scaling-and-squaring, hybrid layout:
//   steps 0..13  : scalar planar [N,3,DHW] ping-pong (coherent phase, issue-optimal)
//   step  14     : scalar planar -> float4 transition
//   steps 15..18 : float4 -> float4 (scattered phase, sector-optimal)
//   step  19     : float4 -> fused planar output
// disp0 = v / 2^20 ; out = [transformation ; displacement], each [2,3,128^3] f32.
//
// Ping-pong bookkeeping (the R5 bug was here):
//   scalar: s even: A->B ; s odd: B->A.  After s=0..13, state lives in A.
//   transition (step 14): A -> f4B.
//   f4:     15: B->A, 16: A->B, 17: B->A, 18: A->B.  State in f4B.
//   final   (step 19): f4B -> out.

#define NVOX (1 << 21)              // 128^3
#define NB 2
#define NC 3
#define TOTAL (NB * NC * NVOX)
#define INIT_SCALE 9.5367431640625e-07f      // 2^-20

__device__ float  g_bufA[TOTAL];
__device__ float  g_bufB[TOTAL];
__device__ float4 g_f4A[NB * NVOX];
__device__ float4 g_f4B[NB * NVOX];
__device__ float  g_base[3 * 128];  // (g+1)*63.5 per axis
__device__ float  g_raw [3 * 128];  // raw identity axis values

// ---------------------------------------------------------------------------
__global__ void __launch_bounds__(256) init_kernel(const float* __restrict__ v) {
    int i = blockIdx.x * 256 + threadIdx.x;
    g_bufA[i] = v[i] * INIT_SCALE;
}

__global__ void base_kernel(const float* __restrict__ grid) {
    int i = threadIdx.x;            // 0..383
    int c = i >> 7;
    int k = i & 127;
    size_t idx;
    if (c == 0)      idx = (size_t)k * 3 + 0;
    else if (c == 1) idx = (size_t)k * 128 * 3 + 1;
    else             idx = (size_t)k * 128 * 128 * 3 + 2;
    float g = grid[idx];
    g_raw[i]  = g;
    g_base[i] = (g + 1.0f) * 63.5f;
}

// ---------------------------------------------------------------------------
// Scalar planar step (coherent phase). OUT_F4: write float4 buffer instead.
template <bool OUT_F4>
__global__ void __launch_bounds__(256) step_scalar(const float* __restrict__ src,
                                                   float* __restrict__ dst,
                                                   float4* __restrict__ df4) {
    int t   = blockIdx.x * 256 + threadIdx.x;    // over NB*NVOX
    int n   = t >> 21;
    int vox = t & (NVOX - 1);
    int x = vox & 127;
    int y = (vox >> 7) & 127;
    int z = vox >> 14;

    const float* s = src + (size_t)n * NC * NVOX;

    float dx = s[vox];
    float dy = s[NVOX + vox];
    float dz = s[2 * NVOX + vox];

    float ix = fminf(fmaxf(fmaf(dx, 63.5f, g_base[x]),        0.0f), 127.0f);
    float iy = fminf(fmaxf(fmaf(dy, 63.5f, g_base[128 + y]),  0.0f), 127.0f);
    float iz = fminf(fmaxf(fmaf(dz, 63.5f, g_base[256 + z]),  0.0f), 127.0f);

    int x0 = (int)ix;  float fx = ix - (float)x0;
    int y0 = (int)iy;  float fy = iy - (float)y0;
    int z0 = (int)iz;  float fz = iz - (float)z0;
    int x1 = min(x0 + 1, 127);
    int y1 = min(y0 + 1, 127);
    int z1 = min(z0 + 1, 127);

    float gx0 = 1.0f - fx, gy0 = 1.0f - fy, gz0 = 1.0f - fz;

    int zy00 = (z0 << 14) + (y0 << 7);
    int zy01 = (z0 << 14) + (y1 << 7);
    int zy10 = (z1 << 14) + (y0 << 7);
    int zy11 = (z1 << 14) + (y1 << 7);
    int i000 = zy00 + x0, i001 = zy00 + x1;
    int i010 = zy01 + x0, i011 = zy01 + x1;
    int i100 = zy10 + x0, i101 = zy10 + x1;
    int i110 = zy11 + x0, i111 = zy11 + x1;

    float w000 = gz0 * gy0 * gx0, w001 = gz0 * gy0 * fx;
    float w010 = gz0 * fy  * gx0, w011 = gz0 * fy  * fx;
    float w100 = fz  * gy0 * gx0, w101 = fz  * gy0 * fx;
    float w110 = fz  * fy  * gx0, w111 = fz  * fy  * fx;

    float a0 = s[i000],  a1 = s[i001];
    float a2 = s[i010],  a3 = s[i011];
    float a4 = s[i100],  a5 = s[i101];
    float a6 = s[i110],  a7 = s[i111];
    const float* s1 = s + NVOX;
    float b0 = s1[i000], b1 = s1[i001];
    float b2 = s1[i010], b3 = s1[i011];
    float b4 = s1[i100], b5 = s1[i101];
    float b6 = s1[i110], b7 = s1[i111];
    const float* s2 = s + 2 * NVOX;
    float c0 = s2[i000], c1 = s2[i001];
    float c2 = s2[i010], c3 = s2[i011];
    float c4 = s2[i100], c5 = s2[i101];
    float c6 = s2[i110], c7 = s2[i111];

    float rx = dx + a0*w000 + a1*w001 + a2*w010 + a3*w011
                  + a4*w100 + a5*w101 + a6*w110 + a7*w111;
    float ry = dy + b0*w000 + b1*w001 + b2*w010 + b3*w011
                  + b4*w100 + b5*w101 + b6*w110 + b7*w111;
    float rz = dz + c0*w000 + c1*w001 + c2*w010 + c3*w011
                  + c4*w100 + c5*w101 + c6*w110 + c7*w111;

    if (!OUT_F4) {
        float* d = dst + (size_t)n * NC * NVOX;
        d[vox]            = rx;
        d[NVOX + vox]     = ry;
        d[2 * NVOX + vox] = rz;
    } else {
        float4 r; r.x = rx; r.y = ry; r.z = rz; r.w = 0.0f;
        df4[t] = r;
    }
}

// ---------------------------------------------------------------------------
// Float4-layout step (scattered phase). LAST: write fused planar output.
template <bool LAST>
__global__ void __launch_bounds__(256) step_f4(const float4* __restrict__ src,
                                               float4* __restrict__ dst,
                                               float* __restrict__ out) {
    int t   = blockIdx.x * 256 + threadIdx.x;
    int n   = t >> 21;
    int vox = t & (NVOX - 1);
    int x = vox & 127;
    int y = (vox >> 7) & 127;
    int z = vox >> 14;

    const float4* s = src + ((size_t)n << 21);
    float4 d4 = s[vox];

    float ix = fminf(fmaxf(fmaf(d4.x, 63.5f, g_base[x]),       0.0f), 127.0f);
    float iy = fminf(fmaxf(fmaf(d4.y, 63.5f, g_base[128 + y]), 0.0f), 127.0f);
    float iz = fminf(fmaxf(fmaf(d4.z, 63.5f, g_base[256 + z]), 0.0f), 127.0f);

    int x0 = (int)ix;  float fx = ix - (float)x0;
    int y0 = (int)iy;  float fy = iy - (float)y0;
    int z0 = (int)iz;  float fz = iz - (float)z0;
    int x1 = min(x0 + 1, 127);
    int y1 = min(y0 + 1, 127);
    int z1 = min(z0 + 1, 127);

    int zy00 = (z0 << 14) + (y0 << 7);
    int zy01 = (z0 << 14) + (y1 << 7);
    int zy10 = (z1 << 14) + (y0 << 7);
    int zy11 = (z1 << 14) + (y1 << 7);

    float4 c000 = s[zy00 + x0], c001 = s[zy00 + x1];
    float4 c010 = s[zy01 + x0], c011 = s[zy01 + x1];
    float4 c100 = s[zy10 + x0], c101 = s[zy10 + x1];
    float4 c110 = s[zy11 + x0], c111 = s[zy11 + x1];

    float gx0 = 1.0f - fx, gy0 = 1.0f - fy, gz0 = 1.0f - fz;
    float w000 = gz0 * gy0 * gx0, w001 = gz0 * gy0 * fx;
    float w010 = gz0 * fy  * gx0, w011 = gz0 * fy  * fx;
    float w100 = fz  * gy0 * gx0, w101 = fz  * gy0 * fx;
    float w110 = fz  * fy  * gx0, w111 = fz  * fy  * fx;

    float rx = d4.x + c000.x*w000 + c001.x*w001 + c010.x*w010 + c011.x*w011
                    + c100.x*w100 + c101.x*w101 + c110.x*w110 + c111.x*w111;
    float ry = d4.y + c000.y*w000 + c001.y*w001 + c010.y*w010 + c011.y*w011
                    + c100.y*w100 + c101.y*w101 + c110.y*w110 + c111.y*w111;
    float rz = d4.z + c000.z*w000 + c001.z*w001 + c010.z*w010 + c011.z*w011
                    + c100.z*w100 + c101.z*w101 + c110.z*w110 + c111.z*w111;

    if (!LAST) {
        float4 r; r.x = rx; r.y = ry; r.z = rz; r.w = 0.0f;
        dst[t] = r;
    } else {
        size_t pb = (size_t)n * NC << 21;
        out[pb + vox]                    = g_raw[x]       + rx;
        out[pb + NVOX + vox]             = g_raw[128 + y] + ry;
        out[pb + 2 * NVOX + vox]         = g_raw[256 + z] + rz;
        out[TOTAL + pb + vox]            = rx;
        out[TOTAL + pb + NVOX + vox]     = ry;
        out[TOTAL + pb + 2 * NVOX + vox] = rz;
    }
}

// ---------------------------------------------------------------------------
extern "C" void kernel_launch(void* const* d_in, const int* in_sizes, int n_in,
                              void* d_out, int out_size) {
    const float* v    = (const float*)d_in[0];
    const float* grid = (const float*)d_in[1];
    float* out = (float*)d_out;

    float *A, *B; float4 *f4A, *f4B;
    cudaGetSymbolAddress((void**)&A,   g_bufA);
    cudaGetSymbolAddress((void**)&B,   g_bufB);
    cudaGetSymbolAddress((void**)&f4A, g_f4A);
    cudaGetSymbolAddress((void**)&f4B, g_f4B);

    const int blocks = (NB * NVOX) / 256;

    init_kernel<<<TOTAL / 256, 256>>>(v);
    base_kernel<<<1, 384>>>(grid);

    // steps 0..13 : scalar ping-pong. even s: A->B, odd s: B->A.
    // s=13 (odd) writes A  => state after 14 steps is in A.
    for (int s = 0; s < 14; s++) {
        const float* src = (s & 1) ? B : A;
        float*       dst = (s & 1) ? A : B;
        step_scalar<false><<<blocks, 256>>>(src, dst, nullptr);
    }
    // step 14 : scalar(A) -> float4(f4B)
    step_scalar<true><<<blocks, 256>>>(A, nullptr, f4B);
    // steps 15..18 : f4B->f4A, f4A->f4B, f4B->f4A, f4A->f4B  => state in f4B
    step_f4<false><<<blocks, 256>>>(f4B, f4A, nullptr);
    step_f4<false><<<blocks, 256>>>(f4A, f4B, nullptr);
    step_f4<false><<<blocks, 256>>>(f4B, f4A, nullptr);
    step_f4<false><<<blocks, 256>>>(f4A, f4B, nullptr);
    // step 19 : float4(f4B) -> fused planar out
    step_f4<true><<<blocks, 256>>>(f4B, nullptr, out);
}